// round 5
// baseline (speedup 1.0000x reference)
#include <cuda_runtime.h>

// CfC recurrent kernel. B=256, S=2048, C=64, U=128, H=256.
// Persistent: 64 CTAs x 256 threads, each CTA owns 4 batch rows and runs the
// full 2048-step scan. W0 (192x256 fp32) + biases live in SMEM; the four head
// matrices (256x512 fp32 combined) are streamed from L2 each step with a
// 16-deep register prefetch. All accumulation uses packed fp32x2 FMA (FFMA2).

typedef unsigned long long u64;

#define NB 256
#define NS 2048
#define NC 64
#define NU 128
#define NH 256
#define KTOT 192
#define BBROWS 4
#define NTHR 256

// SMEM layout (float offsets)
#define OFF_W0   0                       // [192][256]
#define OFF_FEAT (OFF_W0 + 192 * 256)    // [192][4]   (x part 0..63, h part 64..191)
#define OFF_FSM  (OFF_FEAT + 192 * 4)    // [256][4]   activated backbone
#define OFF_P    (OFF_FSM + 256 * 4)     // [512][4]   head pre-activations (col-major-ish)
#define OFF_B0   (OFF_P + 512 * 4)       // [256]
#define OFF_HB   (OFF_B0 + 256)          // [512] = [b1|b2|ba|bb]
#define SMEM_FLOATS (OFF_HB + 512)
#define SMEM_BYTES (SMEM_FLOATS * 4)     // 215040 B

__device__ __forceinline__ u64 pack2(float lo, float hi) {
    u64 r;
    asm("mov.b64 %0, {%1, %2};"
        : "=l"(r) : "r"(__float_as_uint(lo)), "r"(__float_as_uint(hi)));
    return r;
}
__device__ __forceinline__ void fma2(u64& d, u64 a, u64 b) {
    asm("fma.rn.f32x2 %0, %1, %2, %0;" : "+l"(d) : "l"(a), "l"(b));
}
__device__ __forceinline__ float2 unpk(u64 v) {
    unsigned lo, hi;
    asm("mov.b64 {%0, %1}, %2;" : "=r"(lo), "=r"(hi) : "l"(v));
    return make_float2(__uint_as_float(lo), __uint_as_float(hi));
}

__global__ void __launch_bounds__(NTHR, 1) cfc_kernel(
    const float* __restrict__ x_codes,   // [B,S,C]
    const float* __restrict__ h0,        // [B,U]
    const float* __restrict__ tsp,       // [B,S]
    const float* __restrict__ W0,        // [192,256]
    const float* __restrict__ b0,        // [256]
    const float* __restrict__ W1, const float* __restrict__ b1,   // [256,128],[128]
    const float* __restrict__ W2, const float* __restrict__ b2,
    const float* __restrict__ Wa, const float* __restrict__ ba,
    const float* __restrict__ Wb, const float* __restrict__ bb,
    float* __restrict__ out)             // [B,S,U]
{
    extern __shared__ float sm[];
    float* sW0   = sm + OFF_W0;
    float* sfeat = sm + OFF_FEAT;
    float* sfsm  = sm + OFF_FSM;
    float* sp    = sm + OFF_P;
    float* sb0   = sm + OFF_B0;
    float* shb   = sm + OFF_HB;

    const int tid  = threadIdx.x;
    const int brow = blockIdx.x * BBROWS;

    // ---- one-time setup: weights/biases to SMEM, h0 into feat h-part ----
    {
        const float4* W0v = reinterpret_cast<const float4*>(W0);
        float4* sW0v = reinterpret_cast<float4*>(sW0);
        #pragma unroll 4
        for (int i = tid; i < (192 * 256) / 4; i += NTHR) sW0v[i] = W0v[i];
        sb0[tid] = b0[tid];
        if (tid < NU) {
            shb[tid]           = b1[tid];
            shb[NU + tid]      = b2[tid];
            shb[2 * NU + tid]  = ba[tid];
            shb[3 * NU + tid]  = bb[tid];
        }
        for (int t2 = tid; t2 < 4 * NU; t2 += NTHR) {
            int r = t2 >> 7, u = t2 & 127;
            sfeat[(64 + u) * 4 + r] = h0[(size_t)(brow + r) * NU + u];
        }
    }
    __syncthreads();

    // per-thread constants
    const float bg1 = sb0[tid];            // GEMM1 bias for column tid
    const int c0 = tid * 2;                // this thread's 2 head columns (of 512)
    const float bc0 = shb[c0];
    const float bc1 = shb[c0 + 1];
    const float* wp = (tid < 64 ? W1 : tid < 128 ? W2 : tid < 192 ? Wa : Wb)
                      + (c0 & 127);

    const int xr = tid >> 6;               // row for x-load phase
    const int xc = tid & 63;               // channel for x-load phase
    const size_t xbase = ((size_t)(brow + xr) * NS) * NC + xc;

    for (int s = 0; s < NS; ++s) {
        // ---- phase 0: load x_t (scaled) into feat[0..63] ----
        {
            float xv = x_codes[xbase + (size_t)s * NC];
            sfeat[xc * 4 + xr] = (xv - 65.0f) * 0.01f;
        }
        __syncthreads();  // BAR1: feat (x + h) ready

        // ---- phase 1: GEMM1  f = lecun_tanh(feat @ W0 + b0), col = tid ----
        u64 acc01 = pack2(bg1, bg1);
        u64 acc23 = acc01;
        #pragma unroll 8
        for (int k = 0; k < KTOT; ++k) {
            float w = sW0[k * 256 + tid];
            ulonglong2 fv = *reinterpret_cast<const ulonglong2*>(sfeat + k * 4);
            u64 wd = pack2(w, w);
            fma2(acc01, fv.x, wd);
            fma2(acc23, fv.y, wd);
        }
        {
            float2 a01 = unpk(acc01), a23 = unpk(acc23);
            float4 fo;
            fo.x = 1.7159f * tanhf(0.666f * a01.x);
            fo.y = 1.7159f * tanhf(0.666f * a01.y);
            fo.z = 1.7159f * tanhf(0.666f * a23.x);
            fo.w = 1.7159f * tanhf(0.666f * a23.y);
            *reinterpret_cast<float4*>(sfsm + tid * 4) = fo;
        }
        __syncthreads();  // BAR2: f ready

        // ---- phase 2: GEMM2  p = f @ [W1|W2|Wa|Wb] + bias (streamed weights) ----
        u64 qa01 = pack2(bc0, bc0); u64 qa23 = qa01;
        u64 qb01 = pack2(bc1, bc1); u64 qb23 = qb01;
        {
            float2 wbuf[16];
            #pragma unroll
            for (int i = 0; i < 16; ++i)
                wbuf[i] = *reinterpret_cast<const float2*>(wp + i * NU);
            #pragma unroll 1
            for (int kb = 0; kb < NH; kb += 16) {
                const bool pref = (kb + 16 < NH);
                #pragma unroll
                for (int i = 0; i < 16; ++i) {
                    const int k = kb + i;
                    float2 w2 = wbuf[i];
                    if (pref)
                        wbuf[i] = *reinterpret_cast<const float2*>(wp + (k + 16) * NU);
                    ulonglong2 fv = *reinterpret_cast<const ulonglong2*>(sfsm + k * 4);
                    u64 w0d = pack2(w2.x, w2.x);
                    u64 w1d = pack2(w2.y, w2.y);
                    fma2(qa01, fv.x, w0d); fma2(qa23, fv.y, w0d);
                    fma2(qb01, fv.x, w1d); fma2(qb23, fv.y, w1d);
                }
            }
        }
        // stash head pre-activations: p[col][row]
        *reinterpret_cast<u64*>(sp + c0 * 4 + 0) = qa01;
        *reinterpret_cast<u64*>(sp + c0 * 4 + 2) = qa23;
        *reinterpret_cast<u64*>(sp + (c0 + 1) * 4 + 0) = qb01;
        *reinterpret_cast<u64*>(sp + (c0 + 1) * 4 + 2) = qb23;
        __syncthreads();  // BAR3: p ready

        // ---- phase 3: gate + state update + output ----
        #pragma unroll
        for (int t2 = tid; t2 < 4 * NU; t2 += NTHR) {
            int r = t2 >> 7, u = t2 & 127;
            float ff1 = sp[u * 4 + r];
            float ff2 = sp[(NU + u) * 4 + r];
            float ta  = sp[(2 * NU + u) * 4 + r];
            float tb  = sp[(3 * NU + u) * 4 + r];
            float ts  = tsp[(size_t)(brow + r) * NS + s];
            float z   = tb - ta * ts;
            float ti  = 1.0f / (1.0f + expf(-z));
            float nh  = ff1 + ti * (ff2 - ff1);
            sfeat[(64 + u) * 4 + r] = nh;                      // h for next step
            out[((size_t)(brow + r) * NS + s) * NU + u] = nh;  // output
        }
        // no barrier needed: next step's writes (x part of feat / ts reads are
        // from gmem; feat h-part reads happen only after BAR1)
    }
}

extern "C" void kernel_launch(void* const* d_in, const int* in_sizes, int n_in,
                              void* d_out, int out_size) {
    const float* x_codes = (const float*)d_in[0];
    const float* h0      = (const float*)d_in[1];
    const float* tsp     = (const float*)d_in[2];
    const float* W0      = (const float*)d_in[3];
    const float* b0      = (const float*)d_in[4];
    const float* W1      = (const float*)d_in[5];
    const float* b1      = (const float*)d_in[6];
    const float* W2      = (const float*)d_in[7];
    const float* b2      = (const float*)d_in[8];
    const float* Wa      = (const float*)d_in[9];
    const float* ba      = (const float*)d_in[10];
    const float* Wb      = (const float*)d_in[11];
    const float* bb      = (const float*)d_in[12];
    float* out = (float*)d_out;

    cudaFuncSetAttribute(cfc_kernel,
                         cudaFuncAttributeMaxDynamicSharedMemorySize, SMEM_BYTES);

    cfc_kernel<<<NB / BBROWS, NTHR, SMEM_BYTES>>>(
        x_codes, h0, tsp, W0, b0, W1, b1, W2, b2, Wa, ba, Wb, bb, out);
}